// round 8
// baseline (speedup 1.0000x reference)
#include <cuda_runtime.h>
#include <cstdint>

// Fixed problem shapes
constexpr int B_ = 32, N_ = 128, K_ = 16, F_ = 256, D_ = 256;
constexpr int NF_ROWS = B_ * N_ * K_;   // 65536
constexpr int AF_ROWS = B_ * N_;        // 4096
constexpr int NF_TILES = NF_ROWS / 128; // 512
constexpr int AF_TILES = AF_ROWS / 128; // 32

__device__ float g_af[AF_ROWS * D_];    // af scratch (4 MB)

// ---------------- GEMM core config ----------------
constexpr int GT   = 512;     // 16 warps
constexpr int CH   = 32;      // K chunk (floats) = 4 octets
constexpr int NCH  = F_ / CH; // 8
constexpr int SROW = 48;      // smem row stride; 48 % 32 == 16
constexpr int A_ST = 128 * SROW;  // 6144
constexpr int B_ST = 256 * SROW;  // 12288
constexpr int OFF_A = 0;
constexpr int OFF_B = 2 * A_ST;             // 12288
constexpr int GSMEM = OFF_B + 2 * B_ST;     // 36864 floats = 147456 B

// epilogue smem overlay (reuses GEMM smem after mainloop)
constexpr int E_AFB = 0;            // 8*256 af+ba
constexpr int E_BN  = E_AFB + 2048; // 256
constexpr int E_WAL = E_BN + 256;   // 64
constexpr int E_SC  = E_WAL + 64;   // 8*16*4 scores
constexpr int E_AW  = E_SC + 512;   // 8*16*4 attw
constexpr int E_SMK = E_AW + 512;   // 128
constexpr int E_AMK = E_SMK + 128;  // 128
constexpr int E_CTX = E_AMK + 128;  // 8*264
constexpr int E_LN  = E_CTX + 8 * 264; // 2*16

__device__ __forceinline__ float tf32f(float x) {
    float y;
    asm("cvt.rna.tf32.f32 %0, %1;" : "=f"(y) : "f"(x));
    return y;
}
__device__ __forceinline__ void mma_tf32(float c[4], uint32_t a0, uint32_t a1,
                                         uint32_t a2, uint32_t a3,
                                         uint32_t b0, uint32_t b1) {
    asm volatile(
        "mma.sync.aligned.m16n8k8.row.col.f32.tf32.tf32.f32 "
        "{%0,%1,%2,%3},{%4,%5,%6,%7},{%8,%9},{%0,%1,%2,%3};"
        : "+f"(c[0]), "+f"(c[1]), "+f"(c[2]), "+f"(c[3])
        : "r"(a0), "r"(a1), "r"(a2), "r"(a3), "r"(b0), "r"(b1));
}

// gmem loads for one chunk: thread owns A octet [tid] and B octets [tid, tid+512]
__device__ __forceinline__ void ldg_chunk(const float* __restrict__ Ag,
                                          const float* __restrict__ Wg,
                                          int row0, int c, int tid, float4 r[6]) {
    const int arow = tid >> 2, oct = tid & 3;
    const float* pa = Ag + (size_t)(row0 + arow) * F_ + c * CH + oct * 8;
    r[0] = ((const float4*)pa)[0];
    r[1] = ((const float4*)pa)[1];
    const float* pb0 = Wg + (size_t)arow * F_ + c * CH + oct * 8;          // d = tid>>2
    r[2] = ((const float4*)pb0)[0];
    r[3] = ((const float4*)pb0)[1];
    const float* pb1 = Wg + (size_t)(arow + 128) * F_ + c * CH + oct * 8;  // d+128
    r[4] = ((const float4*)pb1)[0];
    r[5] = ((const float4*)pb1)[1];
}

// pack octet [v0..v7] -> slots [k0,k4,k1,k5,k2,k6,k3,k7] with RNA tf32 cvt
__device__ __forceinline__ void pack2(float4 lo, float4 hi, float4& p0, float4& p1) {
    p0 = make_float4(tf32f(lo.x), tf32f(hi.x), tf32f(lo.y), tf32f(hi.y));
    p1 = make_float4(tf32f(lo.z), tf32f(hi.z), tf32f(lo.w), tf32f(hi.w));
}

__device__ __forceinline__ void sts_chunk(float* s, int st, int tid, const float4 r[6]) {
    const int arow = tid >> 2, oct = tid & 3;
    float4 p0, p1;
    // A octet: slot = oct ^ (row & 3)  (2-bit swizzle, slots 0..3, in-bounds)
    {
        float* dst = s + OFF_A + st * A_ST + arow * SROW + ((oct ^ (arow & 3)) * 8);
        pack2(r[0], r[1], p0, p1);
        ((float4*)dst)[0] = p0;
        ((float4*)dst)[1] = p1;
    }
    // B octets (d = arow, arow+128; same oct)
    {
        float* dst = s + OFF_B + st * B_ST + arow * SROW + ((oct ^ (arow & 3)) * 8);
        pack2(r[2], r[3], p0, p1);
        ((float4*)dst)[0] = p0;
        ((float4*)dst)[1] = p1;
    }
    {
        const int d = arow + 128;
        float* dst = s + OFF_B + st * B_ST + d * SROW + ((oct ^ (d & 3)) * 8);
        pack2(r[4], r[5], p0, p1);
        ((float4*)dst)[0] = p0;
        ((float4*)dst)[1] = p1;
    }
}

// GEMM mainloop: fills acc[2][8][4] for warp tile (rb*32 rows, cb*64 cols)
__device__ __forceinline__ void run_gemm(float* s, const float* __restrict__ Ag,
                                         const float* __restrict__ Wg,
                                         int row0, int tid, float acc[2][8][4]) {
    const int lane = tid & 31;
    const int w    = tid >> 5;
    const int l4   = lane & 3;
    const int lr   = lane >> 2;
    const int rb   = w >> 2;
    const int cb   = w & 3;

    float4 rg[6];
    ldg_chunk(Ag, Wg, row0, 0, tid, rg);
    sts_chunk(s, 0, tid, rg);
    ldg_chunk(Ag, Wg, row0, 1, tid, rg);
    __syncthreads();

#pragma unroll
    for (int c = 0; c < NCH; c++) {
        // write stage (c+1)&1 (its previous readers finished at the last barrier)
        if (c + 1 < NCH) sts_chunk(s, (c + 1) & 1, tid, rg);
        if (c + 2 < NCH) ldg_chunk(Ag, Wg, row0, c + 2, tid, rg);

        const float* sa  = s + OFF_A + (c & 1) * A_ST;
        const float* sbb = s + OFF_B + (c & 1) * B_ST;
#pragma unroll
        for (int g = 0; g < 4; g++) {
            // all fragment rows have (row & 3) == (lr & 3) -> shared swizzled offset
            const int soff = ((g ^ (lr & 3)) * 8) + 2 * l4;
            const float* ap = sa + (rb * 32 + lr) * SROW + soff;
            float2 a02_0 = *(const float2*)(ap);
            float2 a13_0 = *(const float2*)(ap + 8 * SROW);
            float2 a02_1 = *(const float2*)(ap + 16 * SROW);
            float2 a13_1 = *(const float2*)(ap + 24 * SROW);
            const float* bp = sbb + (cb * 64 + lr) * SROW + soff;
#pragma unroll
            for (int j = 0; j < 8; j++) {
                float2 b = *(const float2*)(bp + j * 8 * SROW);
                mma_tf32(acc[0][j],
                         __float_as_uint(a02_0.x), __float_as_uint(a13_0.x),
                         __float_as_uint(a02_0.y), __float_as_uint(a13_0.y),
                         __float_as_uint(b.x), __float_as_uint(b.y));
                mma_tf32(acc[1][j],
                         __float_as_uint(a02_1.x), __float_as_uint(a13_1.x),
                         __float_as_uint(a02_1.y), __float_as_uint(a13_1.y),
                         __float_as_uint(b.x), __float_as_uint(b.y));
            }
        }
        __syncthreads();   // readers of stage c&1 and writers of stage (c+1)&1 done
    }
}

// ---------------- kernel A: af GEMM ----------------
__global__ void __launch_bounds__(GT, 1)
af_gemm_kernel(const float* __restrict__ atom, const float* __restrict__ Wa)
{
    extern __shared__ float s[];
    const int tid = threadIdx.x;
    const int row0 = blockIdx.x * 128;
    float acc[2][8][4];
#pragma unroll
    for (int rf = 0; rf < 2; rf++)
#pragma unroll
        for (int j = 0; j < 8; j++)
#pragma unroll
            for (int q = 0; q < 4; q++) acc[rf][j][q] = 0.f;

    run_gemm(s, atom, Wa, row0, tid, acc);

    const int lane = tid & 31, w = tid >> 5;
    const int l4 = lane & 3, lr = lane >> 2;
    const int rb = w >> 2, cb = w & 3;
#pragma unroll
    for (int rf = 0; rf < 2; rf++) {
        int r0 = row0 + rb * 32 + rf * 16 + lr;
#pragma unroll
        for (int j = 0; j < 8; j++) {
            int col = cb * 64 + j * 8 + 2 * l4;
            *(float2*)(g_af + (size_t)r0 * D_ + col)
                = make_float2(acc[rf][j][0], acc[rf][j][1]);
            *(float2*)(g_af + (size_t)(r0 + 8) * D_ + col)
                = make_float2(acc[rf][j][2], acc[rf][j][3]);
        }
    }
}

// ---------------- kernel B: nf GEMM + fused epilogue ----------------
__global__ void __launch_bounds__(GT, 1)
fused_kernel(const float* __restrict__ nbr,
             const float* __restrict__ smask,
             const float* __restrict__ amask,
             const float* __restrict__ ba,
             const float* __restrict__ bn,
             const float* __restrict__ wal,
             const float* __restrict__ bal,
             const float* __restrict__ Wn,
             const float* __restrict__ gam,
             const float* __restrict__ bet,
             float* __restrict__ out)
{
    extern __shared__ float s[];
    const int tid = threadIdx.x;
    const int blk = blockIdx.x;
    const int row0 = blk * 128;

    float acc[2][8][4];
#pragma unroll
    for (int rf = 0; rf < 2; rf++)
#pragma unroll
        for (int j = 0; j < 8; j++)
#pragma unroll
            for (int q = 0; q < 4; q++) acc[rf][j][q] = 0.f;

    run_gemm(s, nbr, Wn, row0, tid, acc);
    // mainloop ends with __syncthreads(): smem free for epilogue overlay

    const int lane = tid & 31, w = tid >> 5;
    const int l4 = lane & 3, lr = lane >> 2;
    const int rb = w >> 2, cb = w & 3;

    // ---- phase 0: cooperative loads ----
    {
        float4 va = ((const float4*)(g_af + (size_t)blk * 8 * D_))[tid];
        int col = (tid * 4) & 255;
        s[E_AFB + tid * 4 + 0] = va.x + ba[col + 0];
        s[E_AFB + tid * 4 + 1] = va.y + ba[col + 1];
        s[E_AFB + tid * 4 + 2] = va.z + ba[col + 2];
        s[E_AFB + tid * 4 + 3] = va.w + ba[col + 3];
        if (tid < 64)                    ((float4*)(s + E_BN))[tid] = ((const float4*)bn)[tid];
        else if (tid < 80)               ((float4*)(s + E_WAL))[tid - 64] = ((const float4*)wal)[tid - 64];
        else if (tid >= 96 && tid < 128) ((float4*)(s + E_SMK))[tid - 96] = ((const float4*)(smask + blk * 128))[tid - 96];
        else if (tid >= 128 && tid < 160)((float4*)(s + E_AMK))[tid - 128] = ((const float4*)(amask + blk * 128))[tid - 128];
    }
    const float bal_s = bal[0];
    __syncthreads();

    // ---- phase 1: per-warp score partials (atom = rb*2+rf, head = cb) ----
#pragma unroll
    for (int rf = 0; rf < 2; rf++) {
        const int a = rb * 2 + rf;
        float s1 = 0.f, s2 = 0.f;
#pragma unroll
        for (int j = 0; j < 8; j++) {
            int c0 = cb * 64 + j * 8 + 2 * l4;
            float af0 = s[E_AFB + a * 256 + c0], af1 = s[E_AFB + a * 256 + c0 + 1];
            float b0  = s[E_BN + c0],            b1  = s[E_BN + c0 + 1];
            float w0  = s[E_WAL + (c0 & 63)],    w1  = s[E_WAL + ((c0 + 1) & 63)];
            float t;
            t = af0 + acc[rf][j][0] + b0; t = (t > 0.f) ? t : 0.2f * t; s1 = fmaf(t, w0, s1);
            t = af1 + acc[rf][j][1] + b1; t = (t > 0.f) ? t : 0.2f * t; s1 = fmaf(t, w1, s1);
            t = af0 + acc[rf][j][2] + b0; t = (t > 0.f) ? t : 0.2f * t; s2 = fmaf(t, w0, s2);
            t = af1 + acc[rf][j][3] + b1; t = (t > 0.f) ? t : 0.2f * t; s2 = fmaf(t, w1, s2);
        }
        s1 += __shfl_xor_sync(0xffffffffu, s1, 1);
        s1 += __shfl_xor_sync(0xffffffffu, s1, 2);
        s2 += __shfl_xor_sync(0xffffffffu, s2, 1);
        s2 += __shfl_xor_sync(0xffffffffu, s2, 2);
        if (l4 == 0) {
            s[E_SC + a * 64 + lr * 4 + cb]       = s1;
            s[E_SC + a * 64 + (lr + 8) * 4 + cb] = s2;
        }
    }
    __syncthreads();

    // ---- phase 2: softmax over k (32 threads: one per (atom, head)) ----
    if (tid < 32) {
        const int a = tid >> 2, h = tid & 3;
        float sc[K_], mx = -3.4e38f;
#pragma unroll
        for (int k = 0; k < K_; k++) {
            sc[k] = s[E_SC + a * 64 + k * 4 + h] + bal_s + s[E_SMK + a * 16 + k];
            mx = fmaxf(mx, sc[k]);
        }
        float ssum = 0.f;
#pragma unroll
        for (int k = 0; k < K_; k++) { sc[k] = __expf(sc[k] - mx); ssum += sc[k]; }
        float inv = 1.f / ssum;
#pragma unroll
        for (int k = 0; k < K_; k++)
            s[E_AW + a * 64 + k * 4 + h] = sc[k] * inv * s[E_AMK + a * 16 + k];
    }
    __syncthreads();

    // ---- phase 3: ctx = sum_k attw * (nf + bn) ----
#pragma unroll
    for (int rf = 0; rf < 2; rf++) {
        const int a = rb * 2 + rf;
        const float aw1 = s[E_AW + a * 64 + lr * 4 + cb];
        const float aw2 = s[E_AW + a * 64 + (lr + 8) * 4 + cb];
#pragma unroll
        for (int j = 0; j < 8; j++) {
            int c0 = cb * 64 + j * 8 + 2 * l4;
            float b0 = s[E_BN + c0], b1 = s[E_BN + c0 + 1];
            float c0v = aw1 * (acc[rf][j][0] + b0) + aw2 * (acc[rf][j][2] + b0);
            float c1v = aw1 * (acc[rf][j][1] + b1) + aw2 * (acc[rf][j][3] + b1);
#pragma unroll
            for (int off = 4; off <= 16; off <<= 1) {
                c0v += __shfl_xor_sync(0xffffffffu, c0v, off);
                c1v += __shfl_xor_sync(0xffffffffu, c1v, off);
            }
            if (lr == 0)
                *(float2*)(s + E_CTX + a * 264 + c0) = make_float2(c0v, c1v);
        }
    }
    __syncthreads();

    // ---- phase 4: LayerNorm + store (half ah handles 4 atoms) ----
    const int dd = tid & 255;
    const int ah = tid >> 8;
    const int wih = (tid & 255) >> 5;
    const float g_d  = gam[dd];
    const float be_d = bet[dd];
#pragma unroll
    for (int i = 0; i < 4; i++) {
        const int a = ah * 4 + i;
        float ctx = s[E_CTX + a * 264 + dd];
        float s1 = ctx, s2 = ctx * ctx;
#pragma unroll
        for (int off = 16; off; off >>= 1) {
            s1 += __shfl_xor_sync(0xffffffffu, s1, off);
            s2 += __shfl_xor_sync(0xffffffffu, s2, off);
        }
        if (lane == 0) {
            s[E_LN + ah * 16 + wih] = s1;
            s[E_LN + ah * 16 + 8 + wih] = s2;
        }
        __syncthreads();
        float S1 = 0.f, S2 = 0.f;
#pragma unroll
        for (int q = 0; q < 8; q++) {
            S1 += s[E_LN + ah * 16 + q];
            S2 += s[E_LN + ah * 16 + 8 + q];
        }
        float mu  = S1 * (1.f / 256.f);
        float var = S2 * (1.f / 256.f) - mu * mu;
        float o = (ctx - mu) * rsqrtf(var + 1e-5f) * g_d + be_d;
        out[(size_t)(blk * 8 + a) * D_ + dd] = o;
        __syncthreads();
    }
}

extern "C" void kernel_launch(void* const* d_in, const int* in_sizes, int n_in,
                              void* d_out, int out_size)
{
    const float* atom_feat = (const float*)d_in[0];
    const float* nbr_feat  = (const float*)d_in[1];
    const float* smask     = (const float*)d_in[2];
    const float* amask     = (const float*)d_in[3];
    const float* Wa        = (const float*)d_in[4];
    const float* ba        = (const float*)d_in[5];
    const float* Wn        = (const float*)d_in[6];
    const float* bn        = (const float*)d_in[7];
    const float* wal       = (const float*)d_in[8];
    const float* bal       = (const float*)d_in[9];
    const float* gam       = (const float*)d_in[10];
    const float* bet       = (const float*)d_in[11];
    float* out = (float*)d_out;

    cudaFuncSetAttribute(af_gemm_kernel,
                         cudaFuncAttributeMaxDynamicSharedMemorySize,
                         GSMEM * (int)sizeof(float));
    cudaFuncSetAttribute(fused_kernel,
                         cudaFuncAttributeMaxDynamicSharedMemorySize,
                         GSMEM * (int)sizeof(float));

    af_gemm_kernel<<<AF_TILES, GT, GSMEM * sizeof(float)>>>(atom_feat, Wa);
    fused_kernel<<<NF_TILES, GT, GSMEM * sizeof(float)>>>(
        nbr_feat, smask, amask, ba, bn, wal, bal, Wn, gam, bet, out);
}

// round 9
// speedup vs baseline: 2.2520x; 2.2520x over previous
#include <cuda_runtime.h>
#include <cstdint>

// Fixed problem shapes
constexpr int B_ = 32, N_ = 128, K_ = 16, F_ = 256, D_ = 256;
constexpr int NF_ROWS = B_ * N_ * K_;   // 65536
constexpr int AF_ROWS = B_ * N_;        // 4096

// scratch (device globals)
__device__ float g_af[AF_ROWS * D_];        // af results (4 MB)
__device__ float g_ctx[AF_ROWS * D_];       // pre-LN context (4 MB)
__device__ float g_wnp[D_ * F_];            // packed Wn (256 KB)
__device__ float g_wap[D_ * F_];            // packed Wa (256 KB)

// ---------------- GEMM core config (256 threads, 128x128 tile) ----------------
constexpr int GT   = 256;     // 8 warps: rb in 0..3 (32 rows), cb in 0..1 (64 cols)
constexpr int CH   = 32;      // K chunk = 4 k8-octets
constexpr int NCH  = F_ / CH; // 8
constexpr int SA   = 36;      // A row stride (raw fp32): bank = 4*lr + l4, conflict-free
constexpr int SBR  = 48;      // B row stride (packed): verified conflict-free LDS.64
constexpr int A_ST = 128 * SA;   // 4608
constexpr int B_ST = 128 * SBR;  // 6144
constexpr int OFF_A = 0;
constexpr int OFF_B = 2 * A_ST;              // 9216
constexpr int GSMEM = OFF_B + 2 * B_ST;      // 21504 floats = 86016 B -> 2 CTAs/SM

// epilogue smem overlay
constexpr int E_AFB = 0;             // 8 atoms x 128 cols (af + ba)
constexpr int E_BN  = E_AFB + 1024;  // 128
constexpr int E_WAL = E_BN + 128;    // 64
constexpr int E_SMK = E_WAL + 64;    // 128
constexpr int E_AMK = E_SMK + 128;   // 128
constexpr int E_SC  = E_AMK + 128;   // 8 atoms x 16 k x 2 heads
constexpr int E_AW  = E_SC + 256;    // same

__device__ __forceinline__ uint32_t s2u(const void* p) {
    return static_cast<uint32_t>(__cvta_generic_to_shared(p));
}
__device__ __forceinline__ void cp16(uint32_t dst, const void* src) {
    asm volatile("cp.async.cg.shared.global [%0], [%1], 16;\n" :: "r"(dst), "l"(src));
}
__device__ __forceinline__ float tf32f(float x) {
    float y;
    asm("cvt.rna.tf32.f32 %0, %1;" : "=f"(y) : "f"(x));
    return y;
}
__device__ __forceinline__ uint32_t tf32u(float x) { return __float_as_uint(tf32f(x)); }

__device__ __forceinline__ void mma_tf32(float c[4], uint32_t a0, uint32_t a1,
                                         uint32_t a2, uint32_t a3,
                                         uint32_t b0, uint32_t b1) {
    asm volatile(
        "mma.sync.aligned.m16n8k8.row.col.f32.tf32.tf32.f32 "
        "{%0,%1,%2,%3},{%4,%5,%6,%7},{%8,%9},{%0,%1,%2,%3};"
        : "+f"(c[0]), "+f"(c[1]), "+f"(c[2]), "+f"(c[3])
        : "r"(a0), "r"(a1), "r"(a2), "r"(a3), "r"(b0), "r"(b1));
}

// issue one chunk: A raw fp32 (128x32), B packed (128 rows x 32 floats)
__device__ __forceinline__ void issue_chunk(float* s, const float* __restrict__ Ag,
                                            const float* __restrict__ Wp,
                                            int row0, int c, int tid) {
    const int st = c & 1;
#pragma unroll
    for (int i = 0; i < 4; i++) {     // A: 1024 cp16
        int idx = tid + i * GT;
        int r = idx >> 3, q = idx & 7;
        cp16(s2u(s + OFF_A + st * A_ST + r * SA + q * 4),
             Ag + (size_t)(row0 + r) * F_ + c * CH + q * 4);
    }
#pragma unroll
    for (int i = 0; i < 4; i++) {     // B: 1024 cp16 (packed rows are contiguous 32 floats)
        int idx = tid + i * GT;
        int r = idx >> 3, q = idx & 7;
        cp16(s2u(s + OFF_B + st * B_ST + r * SBR + q * 4),
             Wp + ((size_t)r * NCH + c) * 32 + q * 4);
    }
}

// GEMM mainloop: acc[2][8][4]; warp tile rows rb*32, cols cb*64 (of 128)
__device__ __forceinline__ void run_gemm(float* s, const float* __restrict__ Ag,
                                         const float* __restrict__ Wp,
                                         int row0, int tid, float acc[2][8][4]) {
    const int lane = tid & 31;
    const int w    = tid >> 5;
    const int l4   = lane & 3;
    const int lr   = lane >> 2;
    const int rb   = w >> 1;      // 0..3
    const int cb   = w & 1;       // 0..1

    issue_chunk(s, Ag, Wp, row0, 0, tid);
    asm volatile("cp.async.commit_group;\n");
    issue_chunk(s, Ag, Wp, row0, 1, tid);
    asm volatile("cp.async.commit_group;\n");

#pragma unroll
    for (int c = 0; c < NCH; c++) {
        if (c == NCH - 1) asm volatile("cp.async.wait_group 0;\n");
        else              asm volatile("cp.async.wait_group 1;\n");
        __syncthreads();

        const float* sa  = s + OFF_A + (c & 1) * A_ST;
        const float* sbb = s + OFF_B + (c & 1) * B_ST;
#pragma unroll
        for (int g = 0; g < 4; g++) {
            const int k0 = g * 8;
            uint32_t a[2][4];
#pragma unroll
            for (int rf = 0; rf < 2; rf++) {
                int r = rb * 32 + rf * 16 + lr;
                a[rf][0] = tf32u(sa[r * SA + k0 + l4]);
                a[rf][1] = tf32u(sa[(r + 8) * SA + k0 + l4]);
                a[rf][2] = tf32u(sa[r * SA + k0 + 4 + l4]);
                a[rf][3] = tf32u(sa[(r + 8) * SA + k0 + 4 + l4]);
            }
            // packed B: slot (g ^ (row&3)), pair (k l4, k l4+4) at 2*l4
            const int soff = ((g ^ (lr & 3)) * 8) + 2 * l4;
            const float* bp = sbb + (cb * 64 + lr) * SBR + soff;
#pragma unroll
            for (int j = 0; j < 8; j++) {
                float2 b = *(const float2*)(bp + j * 8 * SBR);
                mma_tf32(acc[0][j], a[0][0], a[0][1], a[0][2], a[0][3],
                         __float_as_uint(b.x), __float_as_uint(b.y));
                mma_tf32(acc[1][j], a[1][0], a[1][1], a[1][2], a[1][3],
                         __float_as_uint(b.x), __float_as_uint(b.y));
            }
        }
        __syncthreads();
        if (c + 2 < NCH) {
            issue_chunk(s, Ag, Wp, row0, c + 2, tid);
            asm volatile("cp.async.commit_group;\n");
        }
    }
}

// ---------------- W repack kernel ----------------
// packed row d, chunk c: 4 slots of 8; slot s holds octet oct = s ^ (d&3),
// pairs (kb+i, kb+i+4), kb = c*32 + oct*8, tf32-converted.
__global__ void __launch_bounds__(256)
wpack_kernel(const float* __restrict__ Wn, const float* __restrict__ Wa)
{
    int gid = blockIdx.x * 256 + threadIdx.x;      // 0..4095
    int wsel = gid >> 11;
    int rem  = gid & 2047;
    int d = rem >> 3, c = rem & 7;
    const float* src = (wsel ? Wa : Wn) + (size_t)d * F_;
    float* dst = (wsel ? g_wap : g_wnp) + ((size_t)d * NCH + c) * 32;
#pragma unroll
    for (int sl = 0; sl < 4; sl++) {
        int oct = sl ^ (d & 3);
        int kb = c * 32 + oct * 8;
#pragma unroll
        for (int i = 0; i < 4; i++) {
            dst[sl * 8 + 2 * i]     = tf32f(src[kb + i]);
            dst[sl * 8 + 2 * i + 1] = tf32f(src[kb + i + 4]);
        }
    }
}

// ---------------- af GEMM ----------------
__global__ void __launch_bounds__(GT, 2)
af_gemm_kernel(const float* __restrict__ atom)
{
    extern __shared__ float s[];
    const int tid = threadIdx.x;
    const int tile = blockIdx.x >> 1;
    const int hc   = blockIdx.x & 1;
    const int row0 = tile * 128;

    float acc[2][8][4];
#pragma unroll
    for (int rf = 0; rf < 2; rf++)
#pragma unroll
        for (int j = 0; j < 8; j++)
#pragma unroll
            for (int q = 0; q < 4; q++) acc[rf][j][q] = 0.f;

    run_gemm(s, atom, g_wap + (size_t)(hc * 128) * F_, row0, tid, acc);

    const int lane = tid & 31, w = tid >> 5;
    const int l4 = lane & 3, lr = lane >> 2;
    const int rb = w >> 1, cb = w & 1;
#pragma unroll
    for (int rf = 0; rf < 2; rf++) {
        int r0 = row0 + rb * 32 + rf * 16 + lr;
#pragma unroll
        for (int j = 0; j < 8; j++) {
            int col = hc * 128 + cb * 64 + j * 8 + 2 * l4;
            *(float2*)(g_af + (size_t)r0 * D_ + col)
                = make_float2(acc[rf][j][0], acc[rf][j][1]);
            *(float2*)(g_af + (size_t)(r0 + 8) * D_ + col)
                = make_float2(acc[rf][j][2], acc[rf][j][3]);
        }
    }
}

// ---------------- fused nf GEMM + score/softmax/ctx ----------------
__global__ void __launch_bounds__(GT, 2)
fused_kernel(const float* __restrict__ nbr,
             const float* __restrict__ smask,
             const float* __restrict__ amask,
             const float* __restrict__ ba,
             const float* __restrict__ bn,
             const float* __restrict__ wal,
             const float* __restrict__ bal)
{
    extern __shared__ float s[];
    const int tid  = threadIdx.x;
    const int tile = blockIdx.x >> 1;     // 0..511 : 8 atoms each
    const int hc   = blockIdx.x & 1;      // column half (heads hc*2, hc*2+1)
    const int row0 = tile * 128;
    const int atom0 = tile * 8;

    float acc[2][8][4];
#pragma unroll
    for (int rf = 0; rf < 2; rf++)
#pragma unroll
        for (int j = 0; j < 8; j++)
#pragma unroll
            for (int q = 0; q < 4; q++) acc[rf][j][q] = 0.f;

    run_gemm(s, nbr, g_wnp + (size_t)(hc * 128) * F_, row0, tid, acc);
    // last mainloop barrier passed: smem free for overlay

    const int lane = tid & 31, w = tid >> 5;
    const int l4 = lane & 3, lr = lane >> 2;
    const int rb = w >> 1, cb = w & 1;

    // ---- phase 0: loads ----
    {
        int a  = tid >> 5;            // atom 0..7
        int c4 = tid & 31;            // float4 col
        float4 va = *(const float4*)(g_af + (size_t)(atom0 + a) * D_ + hc * 128 + c4 * 4);
        float4 vb = *(const float4*)(ba + hc * 128 + c4 * 4);
        *(float4*)(s + E_AFB + a * 128 + c4 * 4)
            = make_float4(va.x + vb.x, va.y + vb.y, va.z + vb.z, va.w + vb.w);
        if (tid < 32)
            ((float4*)(s + E_BN))[tid] = ((const float4*)(bn + hc * 128))[tid];
        else if (tid < 48)
            ((float4*)(s + E_WAL))[tid - 32] = ((const float4*)wal)[tid - 32];
        else if (tid >= 64 && tid < 96)
            ((float4*)(s + E_SMK))[tid - 64] = ((const float4*)(smask + atom0 * K_))[tid - 64];
        else if (tid >= 96 && tid < 128)
            ((float4*)(s + E_AMK))[tid - 96] = ((const float4*)(amask + atom0 * K_))[tid - 96];
    }
    const float bal_s = bal[0];
    __syncthreads();

    // ---- phase 1: score partials (atom = rb*2+rf, head-local = cb) ----
#pragma unroll
    for (int rf = 0; rf < 2; rf++) {
        const int a = rb * 2 + rf;
        float s1 = 0.f, s2 = 0.f;
#pragma unroll
        for (int j = 0; j < 8; j++) {
            int c0 = cb * 64 + j * 8 + 2 * l4;
            float af0 = s[E_AFB + a * 128 + c0], af1 = s[E_AFB + a * 128 + c0 + 1];
            float b0  = s[E_BN + c0],            b1  = s[E_BN + c0 + 1];
            float w0  = s[E_WAL + ((j * 8 + 2 * l4) & 63)];
            float w1  = s[E_WAL + ((j * 8 + 2 * l4 + 1) & 63)];
            float t;
            t = af0 + acc[rf][j][0] + b0; t = (t > 0.f) ? t : 0.2f * t; s1 = fmaf(t, w0, s1);
            t = af1 + acc[rf][j][1] + b1; t = (t > 0.f) ? t : 0.2f * t; s1 = fmaf(t, w1, s1);
            t = af0 + acc[rf][j][2] + b0; t = (t > 0.f) ? t : 0.2f * t; s2 = fmaf(t, w0, s2);
            t = af1 + acc[rf][j][3] + b1; t = (t > 0.f) ? t : 0.2f * t; s2 = fmaf(t, w1, s2);
        }
        s1 += __shfl_xor_sync(0xffffffffu, s1, 1);
        s1 += __shfl_xor_sync(0xffffffffu, s1, 2);
        s2 += __shfl_xor_sync(0xffffffffu, s2, 1);
        s2 += __shfl_xor_sync(0xffffffffu, s2, 2);
        if (l4 == 0) {
            s[E_SC + a * 32 + lr * 2 + cb]       = s1;   // k = lr
            s[E_SC + a * 32 + (lr + 8) * 2 + cb] = s2;   // k = lr+8
        }
    }
    __syncthreads();

    // ---- phase 2: softmax over k (16 threads: (atom, local head)) ----
    if (tid < 16) {
        const int a = tid >> 1, hh = tid & 1;
        float sc[K_], mx = -3.4e38f;
#pragma unroll
        for (int k = 0; k < K_; k++) {
            sc[k] = s[E_SC + a * 32 + k * 2 + hh] + bal_s + s[E_SMK + a * 16 + k];
            mx = fmaxf(mx, sc[k]);
        }
        float ssum = 0.f;
#pragma unroll
        for (int k = 0; k < K_; k++) { sc[k] = __expf(sc[k] - mx); ssum += sc[k]; }
        float inv = 1.f / ssum;
#pragma unroll
        for (int k = 0; k < K_; k++)
            s[E_AW + a * 32 + k * 2 + hh] = sc[k] * inv * s[E_AMK + a * 16 + k];
    }
    __syncthreads();

    // ---- phase 3: ctx -> g_ctx ----
#pragma unroll
    for (int rf = 0; rf < 2; rf++) {
        const int a = rb * 2 + rf;
        const float aw1 = s[E_AW + a * 32 + lr * 2 + cb];
        const float aw2 = s[E_AW + a * 32 + (lr + 8) * 2 + cb];
#pragma unroll
        for (int j = 0; j < 8; j++) {
            int c0 = cb * 64 + j * 8 + 2 * l4;
            float b0 = s[E_BN + c0], b1 = s[E_BN + c0 + 1];
            float c0v = aw1 * (acc[rf][j][0] + b0) + aw2 * (acc[rf][j][2] + b0);
            float c1v = aw1 * (acc[rf][j][1] + b1) + aw2 * (acc[rf][j][3] + b1);
#pragma unroll
            for (int off = 4; off <= 16; off <<= 1) {
                c0v += __shfl_xor_sync(0xffffffffu, c0v, off);
                c1v += __shfl_xor_sync(0xffffffffu, c1v, off);
            }
            if (lr == 0)
                *(float2*)(g_ctx + (size_t)(atom0 + a) * D_ + hc * 128 + c0)
                    = make_float2(c0v, c1v);
        }
    }
}

// ---------------- LayerNorm kernel (warp per row) ----------------
__global__ void __launch_bounds__(256)
ln_kernel(const float* __restrict__ gam, const float* __restrict__ bet,
          float* __restrict__ out)
{
    const int lane = threadIdx.x & 31;
    const int w    = threadIdx.x >> 5;
    const int row  = blockIdx.x * 8 + w;

    const float* src = g_ctx + (size_t)row * D_;
    float4 v0 = ((const float4*)src)[lane];
    float4 v1 = ((const float4*)src)[lane + 32];
    float s1 = v0.x + v0.y + v0.z + v0.w + v1.x + v1.y + v1.z + v1.w;
    float s2 = v0.x*v0.x + v0.y*v0.y + v0.z*v0.z + v0.w*v0.w
             + v1.x*v1.x + v1.y*v1.y + v1.z*v1.z + v1.w*v1.w;
#pragma unroll
    for (int off = 16; off; off >>= 1) {
        s1 += __shfl_xor_sync(0xffffffffu, s1, off);
        s2 += __shfl_xor_sync(0xffffffffu, s2, off);
    }
    float mu  = s1 * (1.f / 256.f);
    float var = s2 * (1.f / 256.f) - mu * mu;
    float rs  = rsqrtf(var + 1e-5f);

    float4 g0 = ((const float4*)gam)[lane];
    float4 g1 = ((const float4*)gam)[lane + 32];
    float4 b0 = ((const float4*)bet)[lane];
    float4 b1 = ((const float4*)bet)[lane + 32];
    float4 o0, o1;
    o0.x = (v0.x - mu) * rs * g0.x + b0.x;
    o0.y = (v0.y - mu) * rs * g0.y + b0.y;
    o0.z = (v0.z - mu) * rs * g0.z + b0.z;
    o0.w = (v0.w - mu) * rs * g0.w + b0.w;
    o1.x = (v1.x - mu) * rs * g1.x + b1.x;
    o1.y = (v1.y - mu) * rs * g1.y + b1.y;
    o1.z = (v1.z - mu) * rs * g1.z + b1.z;
    o1.w = (v1.w - mu) * rs * g1.w + b1.w;
    ((float4*)(out + (size_t)row * D_))[lane]      = o0;
    ((float4*)(out + (size_t)row * D_))[lane + 32] = o1;
}

extern "C" void kernel_launch(void* const* d_in, const int* in_sizes, int n_in,
                              void* d_out, int out_size)
{
    const float* atom_feat = (const float*)d_in[0];
    const float* nbr_feat  = (const float*)d_in[1];
    const float* smask     = (const float*)d_in[2];
    const float* amask     = (const float*)d_in[3];
    const float* Wa        = (const float*)d_in[4];
    const float* ba        = (const float*)d_in[5];
    const float* Wn        = (const float*)d_in[6];
    const float* bn        = (const float*)d_in[7];
    const float* wal       = (const float*)d_in[8];
    const float* bal       = (const float*)d_in[9];
    const float* gam       = (const float*)d_in[10];
    const float* bet       = (const float*)d_in[11];
    float* out = (float*)d_out;

    cudaFuncSetAttribute(af_gemm_kernel,
                         cudaFuncAttributeMaxDynamicSharedMemorySize,
                         GSMEM * (int)sizeof(float));
    cudaFuncSetAttribute(fused_kernel,
                         cudaFuncAttributeMaxDynamicSharedMemorySize,
                         GSMEM * (int)sizeof(float));

    wpack_kernel<<<16, 256>>>(Wn, Wa);
    af_gemm_kernel<<<64, GT, GSMEM * sizeof(float)>>>(atom_feat);
    fused_kernel<<<1024, GT, GSMEM * sizeof(float)>>>(
        nbr_feat, smask, amask, ba, bn, wal, bal);
    ln_kernel<<<AF_ROWS / 8, 256>>>(gam, bet, out);
}

// round 11
// speedup vs baseline: 2.6541x; 1.1786x over previous
#include <cuda_runtime.h>
#include <cstdint>

// Fixed problem shapes
constexpr int B_ = 32, N_ = 128, K_ = 16, F_ = 256, D_ = 256;
constexpr int NF_TILES = 512;   // 128-row nbr tiles
constexpr int AF_TILES = 32;

// scratch (device globals)
__device__ float g_af[4096 * 256];     // af results (4 MB)
__device__ float g_ctx[4096 * 256];    // pre-LN context (4 MB)
__device__ float g_wnp[256 * 256];     // tf32-rounded Wn (row-major)
__device__ float g_wap[256 * 256];     // tf32-rounded Wa

// ---------------- GEMM core config (256 thr, 128x128 tile, 3-stage) ----------------
constexpr int GT     = 256;      // 8 warps: rb 0..3 (32 rows), cb 0..1 (64 cols)
constexpr int CH     = 32;       // K chunk
constexpr int NCH    = 8;
constexpr int STG_FL = 8192;     // stage: A 128x32 (4096) + B 128x32 (4096), unpadded swizzled
constexpr int SMEM_FL = 3 * STG_FL;   // 24576 floats = 98304 B -> 2 CTAs/SM

// epilogue smem overlay (aliases stage 0; written after mainloop)
constexpr int E_AFB = 0;             // 8 atoms x 128 cols (af + ba)
constexpr int E_BN  = E_AFB + 1024;  // 128
constexpr int E_WAL = E_BN + 128;    // 64
constexpr int E_SMK = E_WAL + 64;    // 128
constexpr int E_AMK = E_SMK + 128;   // 128
constexpr int E_SC  = E_AMK + 128;   // 8 atoms x 16 k x 2 heads
constexpr int E_AW  = E_SC + 256;

__device__ __forceinline__ uint32_t s2u(const void* p) {
    return static_cast<uint32_t>(__cvta_generic_to_shared(p));
}
__device__ __forceinline__ void cp16(uint32_t dst, const void* src) {
    asm volatile("cp.async.cg.shared.global [%0], [%1], 16;\n" :: "r"(dst), "l"(src));
}
__device__ __forceinline__ float tf32f(float x) {
    float y;
    asm("cvt.rna.tf32.f32 %0, %1;" : "=f"(y) : "f"(x));
    return y;
}
__device__ __forceinline__ uint32_t tf32u(float x) { return __float_as_uint(tf32f(x)); }

__device__ __forceinline__ void mma_tf32(float c[4], uint32_t a0, uint32_t a1,
                                         uint32_t a2, uint32_t a3,
                                         uint32_t b0, uint32_t b1) {
    asm volatile(
        "mma.sync.aligned.m16n8k8.row.col.f32.tf32.tf32.f32 "
        "{%0,%1,%2,%3},{%4,%5,%6,%7},{%8,%9},{%0,%1,%2,%3};"
        : "+f"(c[0]), "+f"(c[1]), "+f"(c[2]), "+f"(c[3])
        : "r"(a0), "r"(a1), "r"(a2), "r"(a3), "r"(b0), "r"(b1));
}

// issue one chunk into stage c%3: A raw fp32, B pre-rounded tf32; both XOR-swizzled dst
__device__ __forceinline__ void issue_chunk(float* s, const float* __restrict__ Ag,
                                            const float* __restrict__ Wp,
                                            int row0, int c, int tid) {
    const int stg = (c % 3) * STG_FL;
#pragma unroll
    for (int i = 0; i < 4; i++) {
        int id  = tid + i * GT;          // 0..1023
        int row = id >> 3, c4 = id & 7;
        int sw  = (c4 ^ (row & 7)) << 2; // 16B-granule swizzle
        cp16(s2u(s + stg + row * CH + sw),
             Ag + (size_t)(row0 + row) * F_ + c * CH + c4 * 4);
        cp16(s2u(s + stg + 4096 + row * CH + sw),
             Wp + (size_t)row * F_ + c * CH + c4 * 4);
    }
}

// GEMM mainloop: acc[2][8][4]; warp tile rows rb*32, cols cb*64 (of 128)
__device__ __forceinline__ void run_gemm(float* s, const float* __restrict__ Ag,
                                         const float* __restrict__ Wp,
                                         int row0, int tid, float acc[2][8][4]) {
    const int lane = tid & 31;
    const int w    = tid >> 5;
    const int l4   = lane & 3;
    const int lr   = lane >> 2;
    const int rb   = w >> 1;      // 0..3
    const int cb   = w & 1;       // 0..1

    issue_chunk(s, Ag, Wp, row0, 0, tid);
    asm volatile("cp.async.commit_group;\n");
    issue_chunk(s, Ag, Wp, row0, 1, tid);
    asm volatile("cp.async.commit_group;\n");

#pragma unroll
    for (int c = 0; c < NCH; c++) {
        if (c == NCH - 1) asm volatile("cp.async.wait_group 0;\n");
        else              asm volatile("cp.async.wait_group 1;\n");
        __syncthreads();   // chunk c visible to all; stage (c+2)%3 reads (iter c-1) done
        if (c + 2 < NCH) {
            issue_chunk(s, Ag, Wp, row0, c + 2, tid);
            asm volatile("cp.async.commit_group;\n");
        }

        const float* sa  = s + (c % 3) * STG_FL;
        const float* sbb = sa + 4096;
#pragma unroll
        for (int g = 0; g < 4; g++) {
            const int u    = (2 * g) ^ lr;
            const int off0 = (u << 2) + l4;          // k = g*8 + l4
            const int off1 = ((u ^ 1) << 2) + l4;    // k = g*8 + 4 + l4
            uint32_t a[2][4];
#pragma unroll
            for (int rf = 0; rf < 2; rf++) {
                const float* ap = sa + (rb * 32 + rf * 16 + lr) * CH;
                a[rf][0] = tf32u(ap[off0]);
                a[rf][1] = tf32u(ap[8 * CH + off0]);
                a[rf][2] = tf32u(ap[off1]);
                a[rf][3] = tf32u(ap[8 * CH + off1]);
            }
            const float* bp = sbb + (cb * 64 + lr) * CH;
#pragma unroll
            for (int j = 0; j < 8; j++) {
                uint32_t b0 = __float_as_uint(bp[j * 8 * CH + off0]);
                uint32_t b1 = __float_as_uint(bp[j * 8 * CH + off1]);
                mma_tf32(acc[0][j], a[0][0], a[0][1], a[0][2], a[0][3], b0, b1);
                mma_tf32(acc[1][j], a[1][0], a[1][1], a[1][2], a[1][3], b0, b1);
            }
        }
    }
}

// ---------------- W repack: plain tf32 rounding, row-major ----------------
__global__ void __launch_bounds__(256)
wpack_kernel(const float* __restrict__ Wn, const float* __restrict__ Wa)
{
    int gid = blockIdx.x * 256 + threadIdx.x;   // 0..32767 float4s
    int wsel = gid >> 14;
    int idx  = gid & 16383;
    const float4 v = ((const float4*)(wsel ? Wa : Wn))[idx];
    float4 o = make_float4(tf32f(v.x), tf32f(v.y), tf32f(v.z), tf32f(v.w));
    ((float4*)(wsel ? g_wap : g_wnp))[idx] = o;
}

// ---------------- af GEMM ----------------
__global__ void __launch_bounds__(GT, 2)
af_gemm_kernel(const float* __restrict__ atom)
{
    extern __shared__ float s[];
    const int tid = threadIdx.x;
    const int tile = blockIdx.x >> 1;
    const int hc   = blockIdx.x & 1;
    const int row0 = tile * 128;

    float acc[2][8][4];
#pragma unroll
    for (int rf = 0; rf < 2; rf++)
#pragma unroll
        for (int j = 0; j < 8; j++)
#pragma unroll
            for (int q = 0; q < 4; q++) acc[rf][j][q] = 0.f;

    run_gemm(s, atom, g_wap + (size_t)(hc * 128) * F_, row0, tid, acc);

    const int lane = tid & 31, w = tid >> 5;
    const int l4 = lane & 3, lr = lane >> 2;
    const int rb = w >> 1, cb = w & 1;
#pragma unroll
    for (int rf = 0; rf < 2; rf++) {
        int r0 = row0 + rb * 32 + rf * 16 + lr;
#pragma unroll
        for (int j = 0; j < 8; j++) {
            int col = hc * 128 + cb * 64 + j * 8 + 2 * l4;
            *(float2*)(g_af + (size_t)r0 * D_ + col)
                = make_float2(acc[rf][j][0], acc[rf][j][1]);
            *(float2*)(g_af + (size_t)(r0 + 8) * D_ + col)
                = make_float2(acc[rf][j][2], acc[rf][j][3]);
        }
    }
}

// ---------------- fused nf GEMM + score/softmax/ctx ----------------
__global__ void __launch_bounds__(GT, 2)
fused_kernel(const float* __restrict__ nbr,
             const float* __restrict__ smask,
             const float* __restrict__ amask,
             const float* __restrict__ ba,
             const float* __restrict__ bn,
             const float* __restrict__ wal,
             const float* __restrict__ bal)
{
    extern __shared__ float s[];
    const int tid  = threadIdx.x;
    const int tile = blockIdx.x >> 1;     // 0..511 : 8 atoms each
    const int hc   = blockIdx.x & 1;      // column half (heads hc*2, hc*2+1)
    const int row0 = tile * 128;
    const int atom0 = tile * 8;

    float acc[2][8][4];
#pragma unroll
    for (int rf = 0; rf < 2; rf++)
#pragma unroll
        for (int j = 0; j < 8; j++)
#pragma unroll
            for (int q = 0; q < 4; q++) acc[rf][j][q] = 0.f;

    run_gemm(s, nbr, g_wnp + (size_t)(hc * 128) * F_, row0, tid, acc);
    // past final barrier: stage-0 smem region [0..8192) safe to overlay
    // (last chunk 7 reads stage 1 at offset 8192; overlay stays below that)

    const int lane = tid & 31, w = tid >> 5;
    const int l4 = lane & 3, lr = lane >> 2;
    const int rb = w >> 1, cb = w & 1;

    // ---- phase 0: loads ----
    {
        int a  = tid >> 5;            // atom 0..7
        int c4 = tid & 31;            // float4 col
        float4 va = *(const float4*)(g_af + (size_t)(atom0 + a) * D_ + hc * 128 + c4 * 4);
        float4 vb = *(const float4*)(ba + hc * 128 + c4 * 4);
        *(float4*)(s + E_AFB + a * 128 + c4 * 4)
            = make_float4(va.x + vb.x, va.y + vb.y, va.z + vb.z, va.w + vb.w);
        if (tid < 32)
            ((float4*)(s + E_BN))[tid] = ((const float4*)(bn + hc * 128))[tid];
        else if (tid < 48)
            ((float4*)(s + E_WAL))[tid - 32] = ((const float4*)wal)[tid - 32];
        else if (tid >= 64 && tid < 96)
            ((float4*)(s + E_SMK))[tid - 64] = ((const float4*)(smask + atom0 * K_))[tid - 64];
        else if (tid >= 96 && tid < 128)
            ((float4*)(s + E_AMK))[tid - 96] = ((const float4*)(amask + atom0 * K_))[tid - 96];
    }
    const float bal_s = bal[0];
    __syncthreads();

    // ---- phase 1: score partials (atom = rb*2+rf, head-local = cb) ----
#pragma unroll
    for (int rf = 0; rf < 2; rf++) {
        const int a = rb * 2 + rf;
        float s1 = 0.f, s2 = 0.f;
#pragma unroll
        for (int j = 0; j < 8; j++) {
            int c0 = cb * 64 + j * 8 + 2 * l4;
            float af0 = s[E_AFB + a * 128 + c0], af1 = s[E_AFB + a * 128 + c0 + 1];
            float b0  = s[E_BN + c0],            b1  = s[E_BN + c0 + 1];
            float w0  = s[E_WAL + ((j * 8 + 2 * l4) & 63)];
            float w1  = s[E_WAL + ((j * 8 + 2 * l4 + 1) & 63)];
            float t;
            t = af0 + acc[rf][j][0] + b0; t = (t > 0.f) ? t : 0.2f * t; s1 = fmaf(t, w0, s1);
            t = af1 + acc[rf][j][1] + b1; t = (t > 0.f) ? t : 0.2f * t; s1 = fmaf(t, w1, s1);
            t = af0 + acc[rf][j][2] + b0; t = (t > 0.f) ? t : 0.2f * t; s2 = fmaf(t, w0, s2);
            t = af1 + acc[rf][j][3] + b1; t = (t > 0.f) ? t : 0.2f * t; s2 = fmaf(t, w1, s2);
        }
        s1 += __shfl_xor_sync(0xffffffffu, s1, 1);
        s1 += __shfl_xor_sync(0xffffffffu, s1, 2);
        s2 += __shfl_xor_sync(0xffffffffu, s2, 1);
        s2 += __shfl_xor_sync(0xffffffffu, s2, 2);
        if (l4 == 0) {
            s[E_SC + a * 32 + lr * 2 + cb]       = s1;   // k = lr
            s[E_SC + a * 32 + (lr + 8) * 2 + cb] = s2;   // k = lr+8
        }
    }
    __syncthreads();

    // ---- phase 2: softmax over k (16 threads: (atom, local head)) ----
    if (tid < 16) {
        const int a = tid >> 1, hh = tid & 1;
        float sc[K_], mx = -3.4e38f;
#pragma unroll
        for (int k = 0; k < K_; k++) {
            sc[k] = s[E_SC + a * 32 + k * 2 + hh] + bal_s + s[E_SMK + a * 16 + k];
            mx = fmaxf(mx, sc[k]);
        }
        float ssum = 0.f;
#pragma unroll
        for (int k = 0; k < K_; k++) { sc[k] = __expf(sc[k] - mx); ssum += sc[k]; }
        float inv = 1.f / ssum;
#pragma unroll
        for (int k = 0; k < K_; k++)
            s[E_AW + a * 32 + k * 2 + hh] = sc[k] * inv * s[E_AMK + a * 16 + k];
    }
    __syncthreads();

    // ---- phase 3: ctx -> g_ctx ----
#pragma unroll
    for (int rf = 0; rf < 2; rf++) {
        const int a = rb * 2 + rf;
        const float aw1 = s[E_AW + a * 32 + lr * 2 + cb];
        const float aw2 = s[E_AW + a * 32 + (lr + 8) * 2 + cb];
#pragma unroll
        for (int j = 0; j < 8; j++) {
            int c0 = cb * 64 + j * 8 + 2 * l4;
            float b0 = s[E_BN + c0], b1 = s[E_BN + c0 + 1];
            float c0v = aw1 * (acc[rf][j][0] + b0) + aw2 * (acc[rf][j][2] + b0);
            float c1v = aw1 * (acc[rf][j][1] + b1) + aw2 * (acc[rf][j][3] + b1);
#pragma unroll
            for (int off = 4; off <= 16; off <<= 1) {
                c0v += __shfl_xor_sync(0xffffffffu, c0v, off);
                c1v += __shfl_xor_sync(0xffffffffu, c1v, off);
            }
            if (lr == 0)
                *(float2*)(g_ctx + (size_t)(atom0 + a) * D_ + hc * 128 + c0)
                    = make_float2(c0v, c1v);
        }
    }
}

// ---------------- LayerNorm (warp per row) ----------------
__global__ void __launch_bounds__(256)
ln_kernel(const float* __restrict__ gam, const float* __restrict__ bet,
          float* __restrict__ out)
{
    const int lane = threadIdx.x & 31;
    const int w    = threadIdx.x >> 5;
    const int row  = blockIdx.x * 8 + w;

    const float* src = g_ctx + (size_t)row * D_;
    float4 v0 = ((const float4*)src)[lane];
    float4 v1 = ((const float4*)src)[lane + 32];
    float s1 = v0.x + v0.y + v0.z + v0.w + v1.x + v1.y + v1.z + v1.w;
    float s2 = v0.x*v0.x + v0.y*v0.y + v0.z*v0.z + v0.w*v0.w
             + v1.x*v1.x + v1.y*v1.y + v1.z*v1.z + v1.w*v1.w;
#pragma unroll
    for (int off = 16; off; off >>= 1) {
        s1 += __shfl_xor_sync(0xffffffffu, s1, off);
        s2 += __shfl_xor_sync(0xffffffffu, s2, off);
    }
    float mu  = s1 * (1.f / 256.f);
    float var = s2 * (1.f / 256.f) - mu * mu;
    float rs  = rsqrtf(var + 1e-5f);

    float4 g0 = ((const float4*)gam)[lane];
    float4 g1 = ((const float4*)gam)[lane + 32];
    float4 b0 = ((const float4*)bet)[lane];
    float4 b1 = ((const float4*)bet)[lane + 32];
    float4 o0, o1;
    o0.x = (v0.x - mu) * rs * g0.x + b0.x;
    o0.y = (v0.y - mu) * rs * g0.y + b0.y;
    o0.z = (v0.z - mu) * rs * g0.z + b0.z;
    o0.w = (v0.w - mu) * rs * g0.w + b0.w;
    o1.x = (v1.x - mu) * rs * g1.x + b1.x;
    o1.y = (v1.y - mu) * rs * g1.y + b1.y;
    o1.z = (v1.z - mu) * rs * g1.z + b1.z;
    o1.w = (v1.w - mu) * rs * g1.w + b1.w;
    ((float4*)(out + (size_t)row * D_))[lane]      = o0;
    ((float4*)(out + (size_t)row * D_))[lane + 32] = o1;
}

extern "C" void kernel_launch(void* const* d_in, const int* in_sizes, int n_in,
                              void* d_out, int out_size)
{
    const float* atom_feat = (const float*)d_in[0];
    const float* nbr_feat  = (const float*)d_in[1];
    const float* smask     = (const float*)d_in[2];
    const float* amask     = (const float*)d_in[3];
    const float* Wa        = (const float*)d_in[4];
    const float* ba        = (const float*)d_in[5];
    const float* Wn        = (const float*)d_in[6];
    const float* bn        = (const float*)d_in[7];
    const float* wal       = (const float*)d_in[8];
    const float* bal       = (const float*)d_in[9];
    const float* gam       = (const float*)d_in[10];
    const float* bet       = (const float*)d_in[11];
    float* out = (float*)d_out;

    cudaFuncSetAttribute(af_gemm_kernel,
                         cudaFuncAttributeMaxDynamicSharedMemorySize,
                         SMEM_FL * (int)sizeof(float));
    cudaFuncSetAttribute(fused_kernel,
                         cudaFuncAttributeMaxDynamicSharedMemorySize,
                         SMEM_FL * (int)sizeof(float));

    wpack_kernel<<<128, 256>>>(Wn, Wa);
    af_gemm_kernel<<<AF_TILES * 2, GT, SMEM_FL * sizeof(float)>>>(atom_feat);
    fused_kernel<<<NF_TILES * 2, GT, SMEM_FL * sizeof(float)>>>(
        nbr_feat, smask, amask, ba, bn, wal, bal);
    ln_kernel<<<4096 / 8, 256>>>(gam, bet, out);
}